// round 1
// baseline (speedup 1.0000x reference)
#include <cuda_runtime.h>
#include <cuda_bf16.h>
#include <math.h>

// ---------------------------------------------------------------------------
// PreQ: two shared-weight MLP passes (300->200->100->50->10, ReLU) viewed as
// GEMMs over M = 2*B = 131072 rows, then per-row 2-qubit fidelity epilogue.
// ---------------------------------------------------------------------------

#define MROWS 131072   // 2 * 65536
#define BQ    65536

// Scratch (device globals; no allocations allowed)
__device__ float g_h1[(size_t)MROWS * 200];
__device__ float g_h2[(size_t)MROWS * 100];
__device__ float g_h3[(size_t)MROWS * 50];
__device__ float g_h4[(size_t)MROWS * 10];

// ---------------------------------------------------------------------------
// GEMM: C[M,N] = act(A[M,K] @ W[N,K]^T + bias[N]), all row-major fp32.
// BM=BN=64, BK=16, 256 threads, 4x4 register tile per thread.
// ---------------------------------------------------------------------------
#define BM 64
#define BN 64
#define BK 16

template<bool RELU>
__global__ void gemm_bias_kernel(const float* __restrict__ A,
                                 const float* __restrict__ W,
                                 const float* __restrict__ bias,
                                 float* __restrict__ C,
                                 int M, int N, int K) {
    __shared__ float As[BK][BM + 4];  // +4 keeps 16B alignment, kills conflicts
    __shared__ float Ws[BK][BN + 4];

    const int tid = threadIdx.x;
    const int m0 = blockIdx.x * BM;
    const int n0 = blockIdx.y * BN;
    const int tx = tid & 15;          // row group (4 rows)
    const int ty = tid >> 4;          // col group (4 cols)

    float acc[4][4];
    #pragma unroll
    for (int i = 0; i < 4; i++)
        #pragma unroll
        for (int j = 0; j < 4; j++) acc[i][j] = 0.f;

    const int ktiles = (K + BK - 1) / BK;
    for (int kt = 0; kt < ktiles; ++kt) {
        const int k0 = kt * BK;
        // Stage A tile (transposed to k-major)
        #pragma unroll
        for (int i = tid; i < BM * BK; i += 256) {
            int r = i >> 4, kk = i & 15;
            int k = k0 + kk;
            As[kk][r] = (k < K) ? A[(size_t)(m0 + r) * K + k] : 0.f;
        }
        // Stage W tile (transposed to k-major)
        #pragma unroll
        for (int i = tid; i < BN * BK; i += 256) {
            int c = i >> 4, kk = i & 15;
            int k = k0 + kk, n = n0 + c;
            Ws[kk][c] = (k < K && n < N) ? W[(size_t)n * K + k] : 0.f;
        }
        __syncthreads();

        #pragma unroll
        for (int kk = 0; kk < BK; ++kk) {
            float a[4], w[4];
            #pragma unroll
            for (int i = 0; i < 4; i++) a[i] = As[kk][tx * 4 + i];
            #pragma unroll
            for (int j = 0; j < 4; j++) w[j] = Ws[kk][ty * 4 + j];
            #pragma unroll
            for (int i = 0; i < 4; i++)
                #pragma unroll
                for (int j = 0; j < 4; j++)
                    acc[i][j] = fmaf(a[i], w[j], acc[i][j]);
        }
        __syncthreads();
    }

    #pragma unroll
    for (int i = 0; i < 4; i++) {
        const int m = m0 + tx * 4 + i;
        #pragma unroll
        for (int j = 0; j < 4; j++) {
            const int n = n0 + ty * 4 + j;
            if (n < N) {
                float v = acc[i][j] + bias[n];
                if (RELU) v = fmaxf(v, 0.f);
                C[(size_t)m * N + n] = v;
            }
        }
    }
}

// ---------------------------------------------------------------------------
// Quantum epilogue.
// U(p) = (Rx(p1) (x) Rx(p1)) @ (Ry(p2) (x) Ry(p3)) @ CRx(p4)
// s = U(p[5:10]) @ U(p[0:5]) @ e0 ; fidelity = |s2^H s1|^2
// CRx(t) = I (x) P0 + Rx(t) (x) P1  (so CRx @ e0 = e0, but we need the
// general action for the second application).
// ---------------------------------------------------------------------------
__device__ __forceinline__ float2 cadd(float2 a, float2 b) {
    return make_float2(a.x + b.x, a.y + b.y);
}
__device__ __forceinline__ float2 csc(float s, float2 a) {
    return make_float2(s * a.x, s * a.y);
}
// (-i*s) * a
__device__ __forceinline__ float2 cni(float s, float2 a) {
    return make_float2(s * a.y, -s * a.x);
}

__device__ void applyU(const float* __restrict__ p, float2 x[4]) {
    // --- CRx(p[4]): acts on (x1, x3) with Rx; x0, x2 untouched ---
    float c4, s4;
    sincosf(0.5f * p[4], &s4, &c4);
    float2 y1 = make_float2(c4 * x[1].x + s4 * x[3].y,
                            c4 * x[1].y - s4 * x[3].x);
    float2 y3 = make_float2(s4 * x[1].y + c4 * x[3].x,
                           -s4 * x[1].x + c4 * x[3].y);
    x[1] = y1; x[3] = y3;

    // --- Ry(p[2]) (x) Ry(p[3]) (real coefficients) ---
    float c2, s2, c3, s3;
    sincosf(0.5f * p[2], &s2, &c2);
    sincosf(0.5f * p[3], &s3, &c3);
    float2 t00 = cadd(csc(c3, x[0]), csc(-s3, x[1]));
    float2 t01 = cadd(csc(s3, x[0]), csc( c3, x[1]));
    float2 t10 = cadd(csc(c3, x[2]), csc(-s3, x[3]));
    float2 t11 = cadd(csc(s3, x[2]), csc( c3, x[3]));
    x[0] = cadd(csc(c2, t00), csc(-s2, t10));
    x[1] = cadd(csc(c2, t01), csc(-s2, t11));
    x[2] = cadd(csc(s2, t00), csc( c2, t10));
    x[3] = cadd(csc(s2, t01), csc( c2, t11));

    // --- Rx(p[1]) (x) Rx(p[1]) : [[c, -i s], [-i s, c]] ---
    float c1, s1;
    sincosf(0.5f * p[1], &s1, &c1);
    float2 u00 = cadd(csc(c1, x[0]), cni(s1, x[1]));
    float2 u01 = cadd(cni(s1, x[0]), csc(c1, x[1]));
    float2 u10 = cadd(csc(c1, x[2]), cni(s1, x[3]));
    float2 u11 = cadd(cni(s1, x[2]), csc(c1, x[3]));
    x[0] = cadd(csc(c1, u00), cni(s1, u10));
    x[1] = cadd(csc(c1, u01), cni(s1, u11));
    x[2] = cadd(cni(s1, u00), csc(c1, u10));
    x[3] = cadd(cni(s1, u01), csc(c1, u11));
}

__global__ void quantum_kernel(const float* __restrict__ L,
                               float* __restrict__ out, int Bn) {
    int b = blockIdx.x * blockDim.x + threadIdx.x;
    if (b >= Bn) return;
    const float* l1 = L + (size_t)(2 * b) * 10;  // mlp(x[:, :300]) row
    const float* l2 = l1 + 10;                   // mlp(x[:, 300:]) row

    float2 s1[4] = {make_float2(1.f, 0.f), make_float2(0.f, 0.f),
                    make_float2(0.f, 0.f), make_float2(0.f, 0.f)};
    applyU(l1, s1);       // U1a
    applyU(l1 + 5, s1);   // U1b

    float2 s2[4] = {make_float2(1.f, 0.f), make_float2(0.f, 0.f),
                    make_float2(0.f, 0.f), make_float2(0.f, 0.f)};
    applyU(l2, s2);       // U2a
    applyU(l2 + 5, s2);   // U2b

    // inner = s2^H s1
    float re = 0.f, im = 0.f;
    #pragma unroll
    for (int i = 0; i < 4; i++) {
        re += s2[i].x * s1[i].x + s2[i].y * s1[i].y;
        im += s2[i].x * s1[i].y - s2[i].y * s1[i].x;
    }
    out[b] = re * re + im * im;
}

// ---------------------------------------------------------------------------
extern "C" void kernel_launch(void* const* d_in, const int* in_sizes, int n_in,
                              void* d_out, int out_size) {
    const float* x  = (const float*)d_in[0];
    const float* W1 = (const float*)d_in[1];
    const float* b1 = (const float*)d_in[2];
    const float* W2 = (const float*)d_in[3];
    const float* b2 = (const float*)d_in[4];
    const float* W3 = (const float*)d_in[5];
    const float* b3 = (const float*)d_in[6];
    const float* W4 = (const float*)d_in[7];
    const float* b4 = (const float*)d_in[8];
    float* out = (float*)d_out;

    float *h1, *h2, *h3, *h4;
    cudaGetSymbolAddress((void**)&h1, g_h1);
    cudaGetSymbolAddress((void**)&h2, g_h2);
    cudaGetSymbolAddress((void**)&h3, g_h3);
    cudaGetSymbolAddress((void**)&h4, g_h4);

    const int M = MROWS;
    // x viewed as [2B, 300] contiguous
    gemm_bias_kernel<true ><<<dim3(M / BM, (200 + BN - 1) / BN), 256>>>(x,  W1, b1, h1, M, 200, 300);
    gemm_bias_kernel<true ><<<dim3(M / BM, (100 + BN - 1) / BN), 256>>>(h1, W2, b2, h2, M, 100, 200);
    gemm_bias_kernel<true ><<<dim3(M / BM, ( 50 + BN - 1) / BN), 256>>>(h2, W3, b3, h3, M,  50, 100);
    gemm_bias_kernel<false><<<dim3(M / BM, ( 10 + BN - 1) / BN), 256>>>(h3, W4, b4, h4, M,  10,  50);

    quantum_kernel<<<BQ / 256, 256>>>(h4, out, BQ);
}

// round 2
// speedup vs baseline: 1.8934x; 1.8934x over previous
#include <cuda_runtime.h>
#include <math.h>

// ---------------------------------------------------------------------------
// PreQ: x viewed as [2B, 300] contiguous rows; shared-weight MLP
// 300->200->100->50 as 3 f32x2-packed GEMMs, then fused layer4 (50->10) +
// 2-qubit fidelity epilogue.
// ---------------------------------------------------------------------------

#define MROWS 131072   // 2 * 65536
#define BQ    65536

__device__ float g_h1[(size_t)MROWS * 200];
__device__ float g_h2[(size_t)MROWS * 100];
__device__ float g_h3[(size_t)MROWS * 50];

// ---------------------------------------------------------------------------
// Packed-FMA GEMM: C[M,N] = act(A[M,K] @ W[N,K]^T + bias), fp32, f32x2 math.
// BM=256, BN=64, BK=16, 256 threads.
// Warp w (0..7) owns n-cols [w*8, w*8+8); lane owns m rows
// {q*64 + lane*2 + r : q in 0..3, r in 0..1}.
// Accumulator pairs run along N (contiguous) -> natural float2 loads of W
// and float2 stores of C. A is stored DUPLICATED in smem: (a,a) per element,
// so FFMA2 needs no broadcast movs.
// Requires K % 4 == 0 (holds: 300, 200, 100).
// ---------------------------------------------------------------------------
#define BMg 256
#define BNg 64
#define BKg 16

__device__ __forceinline__ void ffma2(unsigned long long& d,
                                      unsigned long long a,
                                      unsigned long long b) {
    asm("fma.rn.f32x2 %0, %1, %2, %0;" : "+l"(d) : "l"(a), "l"(b));
}

template<bool RELU>
__global__ __launch_bounds__(256, 2)
void gemm_f32x2(const float* __restrict__ A, const float* __restrict__ W,
                const float* __restrict__ bias, float* __restrict__ C,
                int M, int N, int K) {
    __shared__ __align__(16) float2 Asd[BKg][BMg];  // duplicated A, [k][m] : 32KB
    __shared__ __align__(16) float  Wst[BKg][BNg];  // [k][n]              :  4KB

    const int tid  = threadIdx.x;
    const int lane = tid & 31;
    const int wrp  = tid >> 5;           // n-group
    const int m0   = blockIdx.x * BMg;
    const int n0   = blockIdx.y * BNg;
    const int nw   = wrp * 8;

    unsigned long long acc[4][2][4];
    #pragma unroll
    for (int q = 0; q < 4; q++)
        #pragma unroll
        for (int r = 0; r < 2; r++)
            #pragma unroll
            for (int p = 0; p < 4; p++) acc[q][r][p] = 0ull;

    const int ktiles = (K + BKg - 1) / BKg;
    for (int kt = 0; kt < ktiles; ++kt) {
        const int k0 = kt * BKg;

        // Stage A tile (256 rows x 16 k), duplicated. Coalesced float4 loads.
        #pragma unroll
        for (int i = 0; i < 4; ++i) {
            int fidx = tid + i * 256;
            int row  = fidx >> 2;
            int kq   = fidx & 3;
            int k    = k0 + kq * 4;
            float4 v = make_float4(0.f, 0.f, 0.f, 0.f);
            if (k < K) v = *(const float4*)&A[(size_t)(m0 + row) * K + k];
            Asd[kq * 4 + 0][row] = make_float2(v.x, v.x);
            Asd[kq * 4 + 1][row] = make_float2(v.y, v.y);
            Asd[kq * 4 + 2][row] = make_float2(v.z, v.z);
            Asd[kq * 4 + 3][row] = make_float2(v.w, v.w);
        }
        // Stage W tile (64 n x 16 k).
        {
            int n  = tid >> 2;
            int kq = tid & 3;
            int k  = k0 + kq * 4;
            float4 v = make_float4(0.f, 0.f, 0.f, 0.f);
            if (n0 + n < N && k < K)
                v = *(const float4*)&W[(size_t)(n0 + n) * K + k];
            Wst[kq * 4 + 0][n] = v.x;
            Wst[kq * 4 + 1][n] = v.y;
            Wst[kq * 4 + 2][n] = v.z;
            Wst[kq * 4 + 3][n] = v.w;
        }
        __syncthreads();

        #pragma unroll
        for (int kk = 0; kk < BKg; ++kk) {
            // W pairs: broadcast across the warp (all lanes same n-group)
            ulonglong2 w01 = *(const ulonglong2*)&Wst[kk][nw];
            ulonglong2 w23 = *(const ulonglong2*)&Wst[kk][nw + 4];
            #pragma unroll
            for (int q = 0; q < 4; q++) {
                // A dup pairs: lanes 0..7 cover 128 contiguous bytes -> no conflicts
                ulonglong2 ad = *(const ulonglong2*)&Asd[kk][q * 64 + lane * 2];
                ffma2(acc[q][0][0], ad.x, w01.x);
                ffma2(acc[q][0][1], ad.x, w01.y);
                ffma2(acc[q][0][2], ad.x, w23.x);
                ffma2(acc[q][0][3], ad.x, w23.y);
                ffma2(acc[q][1][0], ad.y, w01.x);
                ffma2(acc[q][1][1], ad.y, w01.y);
                ffma2(acc[q][1][2], ad.y, w23.x);
                ffma2(acc[q][1][3], ad.y, w23.y);
            }
        }
        __syncthreads();
    }

    // Epilogue: bias + optional ReLU, float2 stores (N even everywhere).
    float bn[8];
    #pragma unroll
    for (int j = 0; j < 8; j++)
        bn[j] = (n0 + nw + j < N) ? bias[n0 + nw + j] : 0.f;

    #pragma unroll
    for (int q = 0; q < 4; q++) {
        #pragma unroll
        for (int r = 0; r < 2; r++) {
            int m = m0 + q * 64 + lane * 2 + r;
            #pragma unroll
            for (int p = 0; p < 4; p++) {
                float2 v = *(float2*)&acc[q][r][p];
                int n = n0 + nw + 2 * p;
                v.x += bn[2 * p];
                v.y += bn[2 * p + 1];
                if (RELU) { v.x = fmaxf(v.x, 0.f); v.y = fmaxf(v.y, 0.f); }
                if (n + 1 < N) {
                    *(float2*)&C[(size_t)m * N + n] = v;
                } else if (n < N) {
                    C[(size_t)m * N + n] = v.x;
                }
            }
        }
    }
}

// ---------------------------------------------------------------------------
// Quantum epilogue math (unchanged from verified round-1 kernel).
// ---------------------------------------------------------------------------
__device__ __forceinline__ float2 cadd(float2 a, float2 b) {
    return make_float2(a.x + b.x, a.y + b.y);
}
__device__ __forceinline__ float2 csc(float s, float2 a) {
    return make_float2(s * a.x, s * a.y);
}
__device__ __forceinline__ float2 cni(float s, float2 a) {
    return make_float2(s * a.y, -s * a.x);
}

__device__ void applyU(const float* __restrict__ p, float2 x[4]) {
    float c4, s4;
    sincosf(0.5f * p[4], &s4, &c4);
    float2 y1 = make_float2(c4 * x[1].x + s4 * x[3].y,
                            c4 * x[1].y - s4 * x[3].x);
    float2 y3 = make_float2(s4 * x[1].y + c4 * x[3].x,
                           -s4 * x[1].x + c4 * x[3].y);
    x[1] = y1; x[3] = y3;

    float c2, s2, c3, s3;
    sincosf(0.5f * p[2], &s2, &c2);
    sincosf(0.5f * p[3], &s3, &c3);
    float2 t00 = cadd(csc(c3, x[0]), csc(-s3, x[1]));
    float2 t01 = cadd(csc(s3, x[0]), csc( c3, x[1]));
    float2 t10 = cadd(csc(c3, x[2]), csc(-s3, x[3]));
    float2 t11 = cadd(csc(s3, x[2]), csc( c3, x[3]));
    x[0] = cadd(csc(c2, t00), csc(-s2, t10));
    x[1] = cadd(csc(c2, t01), csc(-s2, t11));
    x[2] = cadd(csc(s2, t00), csc( c2, t10));
    x[3] = cadd(csc(s2, t01), csc( c2, t11));

    float c1, s1;
    sincosf(0.5f * p[1], &s1, &c1);
    float2 u00 = cadd(csc(c1, x[0]), cni(s1, x[1]));
    float2 u01 = cadd(cni(s1, x[0]), csc(c1, x[1]));
    float2 u10 = cadd(csc(c1, x[2]), cni(s1, x[3]));
    float2 u11 = cadd(cni(s1, x[2]), csc(c1, x[3]));
    x[0] = cadd(csc(c1, u00), cni(s1, u10));
    x[1] = cadd(csc(c1, u01), cni(s1, u11));
    x[2] = cadd(cni(s1, u00), csc(c1, u10));
    x[3] = cadd(cni(s1, u01), csc(c1, u11));
}

__device__ __forceinline__ float fidelity_from(const float* l1, const float* l2) {
    float2 s1[4] = {make_float2(1.f, 0.f), make_float2(0.f, 0.f),
                    make_float2(0.f, 0.f), make_float2(0.f, 0.f)};
    applyU(l1, s1);
    applyU(l1 + 5, s1);
    float2 s2[4] = {make_float2(1.f, 0.f), make_float2(0.f, 0.f),
                    make_float2(0.f, 0.f), make_float2(0.f, 0.f)};
    applyU(l2, s2);
    applyU(l2 + 5, s2);
    float re = 0.f, im = 0.f;
    #pragma unroll
    for (int i = 0; i < 4; i++) {
        re += s2[i].x * s1[i].x + s2[i].y * s1[i].y;
        im += s2[i].x * s1[i].y - s2[i].y * s1[i].x;
    }
    return re * re + im * im;
}

// ---------------------------------------------------------------------------
// Fused layer-4 (50 -> 10, no ReLU) + quantum fidelity.
// Block: 128 threads, 128 rows of h3 (= 64 fidelity pairs).
// ---------------------------------------------------------------------------
__global__ __launch_bounds__(128)
void l4_quantum(const float* __restrict__ H3, const float* __restrict__ W4,
                const float* __restrict__ b4, float* __restrict__ out) {
    __shared__ float hs[128][51];   // padded, stride 51 (odd) -> conflict-free
    __shared__ float w4s[10][50];
    __shared__ float b4s[10];
    __shared__ float Ls[128][11];   // per-row layer-4 outputs, padded

    const int tid = threadIdx.x;
    const size_t base = (size_t)blockIdx.x * 128 * 50;

    // Stage h3 tile: 6400 floats, coalesced float2 (50 even -> no straddle).
    for (int i = tid; i < 3200; i += 128) {
        float2 v = *(const float2*)&H3[base + 2 * (size_t)i];
        int row = (2 * i) / 50;
        int col = (2 * i) % 50;
        hs[row][col]     = v.x;
        hs[row][col + 1] = v.y;
    }
    for (int i = tid; i < 500; i += 128) w4s[i / 50][i % 50] = W4[i];
    if (tid < 10) b4s[tid] = b4[tid];
    __syncthreads();

    // Each thread: 10-output dot over its row (w reads broadcast).
    float l[10];
    #pragma unroll
    for (int j = 0; j < 10; j++) l[j] = b4s[j];
    #pragma unroll 5
    for (int k = 0; k < 50; k++) {
        float hv = hs[tid][k];
        #pragma unroll
        for (int j = 0; j < 10; j++) l[j] = fmaf(w4s[j][k], hv, l[j]);
    }
    #pragma unroll
    for (int j = 0; j < 10; j++) Ls[tid][j] = l[j];
    __syncthreads();

    if (tid < 64) {
        // rows (2t, 2t+1) = (mlp(x[:, :300]), mlp(x[:, 300:])) for sample b
        out[(size_t)blockIdx.x * 64 + tid] =
            fidelity_from(&Ls[2 * tid][0], &Ls[2 * tid + 1][0]);
    }
}

// ---------------------------------------------------------------------------
extern "C" void kernel_launch(void* const* d_in, const int* in_sizes, int n_in,
                              void* d_out, int out_size) {
    const float* x  = (const float*)d_in[0];
    const float* W1 = (const float*)d_in[1];
    const float* b1 = (const float*)d_in[2];
    const float* W2 = (const float*)d_in[3];
    const float* b2 = (const float*)d_in[4];
    const float* W3 = (const float*)d_in[5];
    const float* b3 = (const float*)d_in[6];
    const float* W4 = (const float*)d_in[7];
    const float* b4 = (const float*)d_in[8];
    float* out = (float*)d_out;

    float *h1, *h2, *h3;
    cudaGetSymbolAddress((void**)&h1, g_h1);
    cudaGetSymbolAddress((void**)&h2, g_h2);
    cudaGetSymbolAddress((void**)&h3, g_h3);

    const int M = MROWS;
    gemm_f32x2<true ><<<dim3(M / BMg, 4), 256>>>(x,  W1, b1, h1, M, 200, 300);
    gemm_f32x2<true ><<<dim3(M / BMg, 2), 256>>>(h1, W2, b2, h2, M, 100, 200);
    gemm_f32x2<true ><<<dim3(M / BMg, 1), 256>>>(h2, W3, b3, h3, M,  50, 100);
    l4_quantum<<<M / 128, 128>>>(h3, W4, b4, out);
}

// round 4
// speedup vs baseline: 4.4875x; 2.3701x over previous
#include <cuda_runtime.h>
#include <cuda_bf16.h>
#include <math.h>
#include <cstdint>

// ---------------------------------------------------------------------------
// PreQ via mma.sync (baseline PTX, no sm_103a-only features):
// x viewed as [2B,300]; MLP 300->200->100->50 as split-bf16 (3-MMA fp32
// emulation) tensor GEMMs, then fused layer4 (50->10) + 2-qubit fidelity.
// ---------------------------------------------------------------------------

#define MROWS 131072   // 2 * 65536

__device__ float g_h1[(size_t)MROWS * 200];
__device__ float g_h2[(size_t)MROWS * 100];
__device__ float g_h3[(size_t)MROWS * 50];

// ---------------------------------------------------------------------------
// Split helpers
// ---------------------------------------------------------------------------
__device__ __forceinline__ uint32_t pack_bf(__nv_bfloat16 a, __nv_bfloat16 b) {
    __nv_bfloat162 t(a, b);
    return *reinterpret_cast<uint32_t*>(&t);
}
__device__ __forceinline__ void split2(float f0, float f1,
                                       uint32_t& hi, uint32_t& lo) {
    __nv_bfloat16 h0 = __float2bfloat16(f0);
    __nv_bfloat16 h1 = __float2bfloat16(f1);
    __nv_bfloat16 l0 = __float2bfloat16(f0 - __bfloat162float(h0));
    __nv_bfloat16 l1 = __float2bfloat16(f1 - __bfloat162float(h1));
    hi = pack_bf(h0, h1);
    lo = pack_bf(l0, l1);
}

// mma.sync m16n8k16 bf16 -> f32 accumulate (baseline sm_80+ feature)
__device__ __forceinline__ void mma16816(float c[4],
                                         uint32_t a0, uint32_t a1,
                                         uint32_t a2, uint32_t a3,
                                         uint32_t b0, uint32_t b1) {
    asm volatile(
        "mma.sync.aligned.m16n8k16.row.col.f32.bf16.bf16.f32 "
        "{%0,%1,%2,%3}, {%4,%5,%6,%7}, {%8,%9}, {%0,%1,%2,%3};"
        : "+f"(c[0]), "+f"(c[1]), "+f"(c[2]), "+f"(c[3])
        : "r"(a0), "r"(a1), "r"(a2), "r"(a3), "r"(b0), "r"(b1));
}

// SMEM layout: per matrix row, per 32-k chunk: 2 k-steps x 4 entries x 16B.
// Entry (row, s, t) = {hi(k=2t,2t+1), lo(k=2t,2t+1), hi(k=2t+8,+9), lo(...)}
// relative to k-step s. Row stride 192B -> LDS.128 phase-conflict-free.
#define ROWB 192

__device__ __forceinline__ void put_pair(char* buf, int row, int s, int q,
                                         float f0, float f1) {
    uint32_t hi, lo;
    split2(f0, f1, hi, lo);
    *(uint2*)(buf + row * ROWB + s * 64 + (q & 3) * 16 + (q >> 2) * 8) =
        make_uint2(hi, lo);
}

// ---------------------------------------------------------------------------
// Split-bf16 GEMM: C[M,Ntrue] = act(A[M,K] @ W[Ntrue,K]^T + bias).
// CTA = 128 rows x Ntrue cols; 8 warps, warp w owns m16 tile rows [16w,16w+16).
// NTILES = ceil(Ntrue/8). K processed in 32-k chunks, double buffered.
// ---------------------------------------------------------------------------
template<int NTILES, bool RELU>
__global__ __launch_bounds__(256, 1)
void gemm_mma(const float* __restrict__ A, const float* __restrict__ W,
              const float* __restrict__ bias, float* __restrict__ C,
              int Ntrue, int K, int nchunks) {
    extern __shared__ __align__(16) char sm[];
    constexpr int NR     = NTILES * 8;
    constexpr int ABYTES = 128 * ROWB;
    constexpr int STAGE  = ABYTES + NR * ROWB;

    const int tid  = threadIdx.x;
    const int wid  = tid >> 5;
    const int lane = tid & 31;
    const int g    = lane >> 2;      // group row
    const int t    = lane & 3;       // k-pair selector
    const size_t m0 = (size_t)blockIdx.x * 128;

    float acc[NTILES][4];
    #pragma unroll
    for (int j = 0; j < NTILES; j++)
        #pragma unroll
        for (int p = 0; p < 4; p++) acc[j][p] = 0.f;

    auto stage = [&](int c, char* buf) {
        const int k0 = c * 32;
        // A: 128 rows x 32 k = 1024 float4, 4 per thread.
        #pragma unroll
        for (int i = 0; i < 4; i++) {
            int f   = tid + i * 256;
            int row = f >> 3;
            int kq  = f & 7;
            int k   = k0 + kq * 4;
            float4 v = make_float4(0.f, 0.f, 0.f, 0.f);
            if (k < K) v = *(const float4*)(A + (m0 + row) * K + k);
            int s = kq >> 2;
            int q = (kq & 3) * 2;            // pairs q, q+1
            put_pair(buf, row, s, q,     v.x, v.y);
            put_pair(buf, row, s, q + 1, v.z, v.w);
        }
        // W: NR rows x 32 k = NR*8 float4.
        char* wb = buf + ABYTES;
        constexpr int WF = NR * 8;
        #pragma unroll
        for (int i = 0; i < (WF + 255) / 256; i++) {
            int f = tid + i * 256;
            if (f < WF) {
                int row = f >> 3;
                int kq  = f & 7;
                int k   = k0 + kq * 4;
                float4 v = make_float4(0.f, 0.f, 0.f, 0.f);
                if (k < K && row < Ntrue)
                    v = *(const float4*)(W + (size_t)row * K + k);
                int s = kq >> 2;
                int q = (kq & 3) * 2;
                put_pair(wb, row, s, q,     v.x, v.y);
                put_pair(wb, row, s, q + 1, v.z, v.w);
            }
        }
    };

    auto compute = [&](char* buf) {
        char* As = buf;
        char* Ws = buf + ABYTES;
        #pragma unroll
        for (int s = 0; s < 2; s++) {
            // A fragments: {a0hi,a0lo,a2hi,a2lo} / {a1hi,a1lo,a3hi,a3lo}
            uint4 ar0 = *(const uint4*)(As + (wid * 16 + g)     * ROWB + s * 64 + t * 16);
            uint4 ar8 = *(const uint4*)(As + (wid * 16 + g + 8) * ROWB + s * 64 + t * 16);
            #pragma unroll
            for (int j = 0; j < NTILES; j++) {
                // B fragment entry: {b0hi, b0lo, b1hi, b1lo}
                uint4 bb = *(const uint4*)(Ws + (j * 8 + g) * ROWB + s * 64 + t * 16);
                mma16816(acc[j], ar0.x, ar8.x, ar0.z, ar8.z, bb.x, bb.z); // hi*hi
                mma16816(acc[j], ar0.x, ar8.x, ar0.z, ar8.z, bb.y, bb.w); // hi*lo
                mma16816(acc[j], ar0.y, ar8.y, ar0.w, ar8.w, bb.x, bb.z); // lo*hi
            }
        }
    };

    stage(0, sm);
    __syncthreads();
    for (int c = 0; c < nchunks; ++c) {
        if (c + 1 < nchunks) stage(c + 1, sm + ((c + 1) & 1) * STAGE);
        compute(sm + (c & 1) * STAGE);
        __syncthreads();
    }

    // Epilogue: bias + ReLU, float2 stores straight from fragments.
    const size_t r0 = m0 + wid * 16 + g;
    const size_t r1 = r0 + 8;
    #pragma unroll
    for (int j = 0; j < NTILES; j++) {
        int n = j * 8 + t * 2;
        if (n < Ntrue) {
            float2 bb = *(const float2*)(bias + n);
            float v0 = acc[j][0] + bb.x, v1 = acc[j][1] + bb.y;
            float v2 = acc[j][2] + bb.x, v3 = acc[j][3] + bb.y;
            if (RELU) {
                v0 = fmaxf(v0, 0.f); v1 = fmaxf(v1, 0.f);
                v2 = fmaxf(v2, 0.f); v3 = fmaxf(v3, 0.f);
            }
            *(float2*)(C + r0 * Ntrue + n) = make_float2(v0, v1);
            *(float2*)(C + r1 * Ntrue + n) = make_float2(v2, v3);
        }
    }
}

// ---------------------------------------------------------------------------
// Quantum epilogue math (verified rounds 1-2).
// ---------------------------------------------------------------------------
__device__ __forceinline__ float2 cadd(float2 a, float2 b) {
    return make_float2(a.x + b.x, a.y + b.y);
}
__device__ __forceinline__ float2 csc(float s, float2 a) {
    return make_float2(s * a.x, s * a.y);
}
__device__ __forceinline__ float2 cni(float s, float2 a) {
    return make_float2(s * a.y, -s * a.x);
}

__device__ void applyU(const float* __restrict__ p, float2 x[4]) {
    float c4, s4;
    sincosf(0.5f * p[4], &s4, &c4);
    float2 y1 = make_float2(c4 * x[1].x + s4 * x[3].y,
                            c4 * x[1].y - s4 * x[3].x);
    float2 y3 = make_float2(s4 * x[1].y + c4 * x[3].x,
                           -s4 * x[1].x + c4 * x[3].y);
    x[1] = y1; x[3] = y3;

    float c2, s2, c3, s3;
    sincosf(0.5f * p[2], &s2, &c2);
    sincosf(0.5f * p[3], &s3, &c3);
    float2 t00 = cadd(csc(c3, x[0]), csc(-s3, x[1]));
    float2 t01 = cadd(csc(s3, x[0]), csc( c3, x[1]));
    float2 t10 = cadd(csc(c3, x[2]), csc(-s3, x[3]));
    float2 t11 = cadd(csc(s3, x[2]), csc( c3, x[3]));
    x[0] = cadd(csc(c2, t00), csc(-s2, t10));
    x[1] = cadd(csc(c2, t01), csc(-s2, t11));
    x[2] = cadd(csc(s2, t00), csc( c2, t10));
    x[3] = cadd(csc(s2, t01), csc( c2, t11));

    float c1, s1;
    sincosf(0.5f * p[1], &s1, &c1);
    float2 u00 = cadd(csc(c1, x[0]), cni(s1, x[1]));
    float2 u01 = cadd(cni(s1, x[0]), csc(c1, x[1]));
    float2 u10 = cadd(csc(c1, x[2]), cni(s1, x[3]));
    float2 u11 = cadd(cni(s1, x[2]), csc(c1, x[3]));
    x[0] = cadd(csc(c1, u00), cni(s1, u10));
    x[1] = cadd(csc(c1, u01), cni(s1, u11));
    x[2] = cadd(cni(s1, u00), csc(c1, u10));
    x[3] = cadd(cni(s1, u01), csc(c1, u11));
}

__device__ __forceinline__ float fidelity_from(const float* l1, const float* l2) {
    float2 s1[4] = {make_float2(1.f, 0.f), make_float2(0.f, 0.f),
                    make_float2(0.f, 0.f), make_float2(0.f, 0.f)};
    applyU(l1, s1);
    applyU(l1 + 5, s1);
    float2 s2[4] = {make_float2(1.f, 0.f), make_float2(0.f, 0.f),
                    make_float2(0.f, 0.f), make_float2(0.f, 0.f)};
    applyU(l2, s2);
    applyU(l2 + 5, s2);
    float re = 0.f, im = 0.f;
    #pragma unroll
    for (int i = 0; i < 4; i++) {
        re += s2[i].x * s1[i].x + s2[i].y * s1[i].y;
        im += s2[i].x * s1[i].y - s2[i].y * s1[i].x;
    }
    return re * re + im * im;
}

// Fused layer-4 (50 -> 10) + quantum fidelity. 128 rows/block.
__global__ __launch_bounds__(128)
void l4_quantum(const float* __restrict__ H3, const float* __restrict__ W4,
                const float* __restrict__ b4, float* __restrict__ out) {
    __shared__ float hs[128][51];
    __shared__ float w4s[10][50];
    __shared__ float b4s[10];
    __shared__ float Ls[128][11];

    const int tid = threadIdx.x;
    const size_t base = (size_t)blockIdx.x * 128 * 50;

    for (int i = tid; i < 3200; i += 128) {
        float2 v = *(const float2*)&H3[base + 2 * (size_t)i];
        int row = (2 * i) / 50, col = (2 * i) % 50;
        hs[row][col] = v.x;
        hs[row][col + 1] = v.y;
    }
    for (int i = tid; i < 500; i += 128) w4s[i / 50][i % 50] = W4[i];
    if (tid < 10) b4s[tid] = b4[tid];
    __syncthreads();

    float l[10];
    #pragma unroll
    for (int j = 0; j < 10; j++) l[j] = b4s[j];
    #pragma unroll 5
    for (int k = 0; k < 50; k++) {
        float hv = hs[tid][k];
        #pragma unroll
        for (int j = 0; j < 10; j++) l[j] = fmaf(w4s[j][k], hv, l[j]);
    }
    #pragma unroll
    for (int j = 0; j < 10; j++) Ls[tid][j] = l[j];
    __syncthreads();

    if (tid < 64) {
        out[(size_t)blockIdx.x * 64 + tid] =
            fidelity_from(&Ls[2 * tid][0], &Ls[2 * tid + 1][0]);
    }
}

// ---------------------------------------------------------------------------
extern "C" void kernel_launch(void* const* d_in, const int* in_sizes, int n_in,
                              void* d_out, int out_size) {
    const float* x  = (const float*)d_in[0];
    const float* W1 = (const float*)d_in[1];
    const float* b1 = (const float*)d_in[2];
    const float* W2 = (const float*)d_in[3];
    const float* b2 = (const float*)d_in[4];
    const float* W3 = (const float*)d_in[5];
    const float* b3 = (const float*)d_in[6];
    const float* W4 = (const float*)d_in[7];
    const float* b4 = (const float*)d_in[8];
    float* out = (float*)d_out;

    float *h1, *h2, *h3;
    cudaGetSymbolAddress((void**)&h1, g_h1);
    cudaGetSymbolAddress((void**)&h2, g_h2);
    cudaGetSymbolAddress((void**)&h3, g_h3);

    // dyn smem = 2 * (128 + NTILES*8) * 192
    const int SM1 = 2 * (128 + 200) * ROWB;   // 125952
    const int SM2 = 2 * (128 + 104) * ROWB;   //  89088
    const int SM3 = 2 * (128 +  56) * ROWB;   //  70656
    cudaFuncSetAttribute(gemm_mma<25, true>,
                         cudaFuncAttributeMaxDynamicSharedMemorySize, SM1);
    cudaFuncSetAttribute(gemm_mma<13, true>,
                         cudaFuncAttributeMaxDynamicSharedMemorySize, SM2);
    cudaFuncSetAttribute(gemm_mma<7, true>,
                         cudaFuncAttributeMaxDynamicSharedMemorySize, SM3);

    const int MT = MROWS / 128;   // 1024
    gemm_mma<25, true><<<MT, 256, SM1>>>(x,  W1, b1, h1, 200, 300, 10);
    gemm_mma<13, true><<<MT, 256, SM2>>>(h1, W2, b2, h2, 100, 200, 7);
    gemm_mma<7,  true><<<MT, 256, SM3>>>(h2, W3, b3, h3,  50, 100, 4);
    l4_quantum<<<MROWS / 128, 128>>>(h3, W4, b4, out);
}

// round 5
// speedup vs baseline: 4.9755x; 1.1087x over previous
#include <cuda_runtime.h>
#include <cuda_bf16.h>
#include <math.h>
#include <cstdint>

// ---------------------------------------------------------------------------
// PreQ via mma.sync split-bf16 with fragment-ready gmem staging:
//  - W pre-split once into fragment layout (prep kernels)
//  - intermediates stored in fragment layout by the producer epilogue
//  - staging = pure cp.async 16B copies
// ---------------------------------------------------------------------------

#define MROWS 131072   // 2 * 65536
#define ROWB  192      // smem row stride (128B data + 64B pad)

// frag scratch: [row][chunk][128B]
__device__ __align__(16) unsigned char g_h1f[(size_t)MROWS * 896];  // 7 chunks
__device__ __align__(16) unsigned char g_h2f[(size_t)MROWS * 512];  // 4 chunks
__device__ float g_h3[(size_t)MROWS * 50];
__device__ __align__(16) unsigned char g_w1f[200 * 10 * 128];
__device__ __align__(16) unsigned char g_w2f[104 * 7 * 128];
__device__ __align__(16) unsigned char g_w3f[56 * 4 * 128];

// ---------------------------------------------------------------------------
__device__ __forceinline__ uint32_t smem_u32(const void* p) {
    uint32_t a;
    asm("{ .reg .u64 t; cvta.to.shared.u64 t, %1; cvt.u32.u64 %0, t; }"
        : "=r"(a) : "l"(p));
    return a;
}
__device__ __forceinline__ void cpa16(uint32_t dst, const void* src) {
    asm volatile("cp.async.cg.shared.global [%0], [%1], 16;"
                 :: "r"(dst), "l"(src) : "memory");
}
#define CP_COMMIT() asm volatile("cp.async.commit_group;" ::: "memory")
#define CP_WAIT0()  asm volatile("cp.async.wait_group 0;" ::: "memory")

__device__ __forceinline__ uint32_t pack_bf(__nv_bfloat16 a, __nv_bfloat16 b) {
    __nv_bfloat162 t(a, b);
    return *reinterpret_cast<uint32_t*>(&t);
}
__device__ __forceinline__ void split2(float f0, float f1,
                                       uint32_t& hi, uint32_t& lo) {
    __nv_bfloat16 h0 = __float2bfloat16(f0);
    __nv_bfloat16 h1 = __float2bfloat16(f1);
    __nv_bfloat16 l0 = __float2bfloat16(f0 - __bfloat162float(h0));
    __nv_bfloat16 l1 = __float2bfloat16(f1 - __bfloat162float(h1));
    hi = pack_bf(h0, h1);
    lo = pack_bf(l0, l1);
}

__device__ __forceinline__ void mma16816(float c[4],
                                         uint32_t a0, uint32_t a1,
                                         uint32_t a2, uint32_t a3,
                                         uint32_t b0, uint32_t b1) {
    asm volatile(
        "mma.sync.aligned.m16n8k16.row.col.f32.bf16.bf16.f32 "
        "{%0,%1,%2,%3}, {%4,%5,%6,%7}, {%8,%9}, {%0,%1,%2,%3};"
        : "+f"(c[0]), "+f"(c[1]), "+f"(c[2]), "+f"(c[3])
        : "r"(a0), "r"(a1), "r"(a2), "r"(a3), "r"(b0), "r"(b1));
}

// byte offset of the uint2 {hi,lo} for k-pair starting at n within a row's
// fragment image ([chunk][128B] blocks)
__device__ __forceinline__ uint32_t frag_off(int n) {
    return (uint32_t)((n >> 5) * 128 + ((n >> 4) & 1) * 64 +
                      ((n >> 1) & 3) * 16 + (((n >> 1) >> 2) & 1) * 8);
}

// smem entry write used by fp32->frag staging (layer 1 A)
__device__ __forceinline__ void put_pair(char* buf, int row, int s, int q,
                                         float f0, float f1) {
    uint32_t hi, lo;
    split2(f0, f1, hi, lo);
    *(uint2*)(buf + row * ROWB + s * 64 + (q & 3) * 16 + (q >> 2) * 8) =
        make_uint2(hi, lo);
}

// ---------------------------------------------------------------------------
// prep: W[Ntrue,K] fp32 -> fragment image [NR rows][nch chunks][128B]
// ---------------------------------------------------------------------------
__global__ void prep_w_frag(const float* __restrict__ W, unsigned char* Wf,
                            int Ntrue, int K, int nch, int total) {
    int f = blockIdx.x * blockDim.x + threadIdx.x;
    if (f >= total) return;
    const int per_row = nch * 8;
    const int row = f / per_row;
    const int r = f - row * per_row;
    const int c = r >> 3, e = r & 7;
    const int s = e >> 2, q = e & 3;
    const int k0 = c * 32 + s * 16 + q * 2;
    float v0 = 0.f, v1 = 0.f, v2 = 0.f, v3 = 0.f;
    if (row < Ntrue) {
        const float* Wr = W + (size_t)row * K;
        if (k0 < K)     v0 = Wr[k0];
        if (k0 + 1 < K) v1 = Wr[k0 + 1];
        if (k0 + 8 < K) v2 = Wr[k0 + 8];
        if (k0 + 9 < K) v3 = Wr[k0 + 9];
    }
    uint32_t h0, l0, h1, l1;
    split2(v0, v1, h0, l0);
    split2(v2, v3, h1, l1);
    *(uint4*)(Wf + (size_t)row * (nch * 128) + c * 128 + e * 16) =
        make_uint4(h0, l0, h1, l1);
}

// ---------------------------------------------------------------------------
// GEMM: C = act(A @ W^T + bias). 128 rows/CTA, 8 warps, NTILES n8-tiles.
// AMODE: 0 = A is fp32 [M,K] (convert in stage); 1 = A is frag image.
// OMODE: 0 = fp32 out [M,Ntrue]; 1 = frag image out (+ zero pad [padlo,padhi)).
// ---------------------------------------------------------------------------
template<int NTILES, int AMODE, int OMODE, bool RELU>
__global__ __launch_bounds__(256)
void gemm_mma(const void* __restrict__ Asrc, const unsigned char* __restrict__ Wf,
              const float* __restrict__ bias, void* __restrict__ Cout,
              int Ntrue, int K, int nch, int a_rowstride,
              int o_rowstride, int o_padlo, int o_padhi) {
    extern __shared__ __align__(16) char sm[];
    constexpr int NR     = NTILES * 8;
    constexpr int ABYTES = 128 * ROWB;
    constexpr int STAGE  = ABYTES + NR * ROWB;

    const uint32_t sb = smem_u32(sm);
    const int tid  = threadIdx.x;
    const int wid  = tid >> 5;
    const int lane = tid & 31;
    const int g    = lane >> 2;
    const int t    = lane & 3;
    const size_t m0 = (size_t)blockIdx.x * 128;

    float acc[NTILES][4];
    #pragma unroll
    for (int j = 0; j < NTILES; j++)
        #pragma unroll
        for (int p = 0; p < 4; p++) acc[j][p] = 0.f;

    auto stage = [&](int c, int slot) {
        char* buf = sm + slot * STAGE;
        const uint32_t bufb = sb + slot * STAGE;
        if constexpr (AMODE == 0) {
            // A: fp32 -> split-bf16 entries (128 rows x 32 k = 1024 float4)
            const float* A = (const float*)Asrc;
            const int k0 = c * 32;
            #pragma unroll
            for (int i = 0; i < 4; i++) {
                int f   = tid + i * 256;
                int row = f >> 3;
                int kq  = f & 7;
                int k   = k0 + kq * 4;
                float4 v = make_float4(0.f, 0.f, 0.f, 0.f);
                if (k < K) v = *(const float4*)(A + (m0 + row) * (size_t)K + k);
                int s = kq >> 2;
                int q = (kq & 3) * 2;
                put_pair(buf, row, s, q,     v.x, v.y);
                put_pair(buf, row, s, q + 1, v.z, v.w);
            }
        } else {
            // A frag: pure cp.async, 128 rows x 8 entries
            const unsigned char* Af = (const unsigned char*)Asrc;
            #pragma unroll
            for (int i = 0; i < 4; i++) {
                int f   = tid + i * 256;
                int row = f >> 3;
                int e   = f & 7;
                cpa16(bufb + row * ROWB + e * 16,
                      Af + (m0 + row) * (size_t)a_rowstride + c * 128 + e * 16);
            }
        }
        // W frag: pure cp.async, NR rows x 8 entries
        constexpr int WF = NR * 8;
        const uint32_t wb = bufb + ABYTES;
        #pragma unroll
        for (int i = 0; i < (WF + 255) / 256; i++) {
            int f = tid + i * 256;
            if (f < WF) {
                int row = f >> 3;
                int e   = f & 7;
                cpa16(wb + row * ROWB + e * 16,
                      Wf + (size_t)row * (nch * 128) + c * 128 + e * 16);
            }
        }
    };

    auto compute = [&](int slot) {
        char* As = sm + slot * STAGE;
        char* Ws = As + ABYTES;
        #pragma unroll
        for (int s = 0; s < 2; s++) {
            uint4 ar0 = *(const uint4*)(As + (wid * 16 + g)     * ROWB + s * 64 + t * 16);
            uint4 ar8 = *(const uint4*)(As + (wid * 16 + g + 8) * ROWB + s * 64 + t * 16);
            #pragma unroll
            for (int j = 0; j < NTILES; j++) {
                uint4 bb = *(const uint4*)(Ws + (j * 8 + g) * ROWB + s * 64 + t * 16);
                mma16816(acc[j], ar0.x, ar8.x, ar0.z, ar8.z, bb.x, bb.z);
                mma16816(acc[j], ar0.x, ar8.x, ar0.z, ar8.z, bb.y, bb.w);
                mma16816(acc[j], ar0.y, ar8.y, ar0.w, ar8.w, bb.x, bb.z);
            }
        }
    };

    stage(0, 0);
    CP_COMMIT();
    CP_WAIT0();
    __syncthreads();
    for (int c = 0; c < nch; ++c) {
        if (c + 1 < nch) { stage(c + 1, (c + 1) & 1); CP_COMMIT(); }
        compute(c & 1);
        CP_WAIT0();
        __syncthreads();
    }

    // Epilogue
    const size_t r0 = m0 + wid * 16 + g;
    const size_t r1 = r0 + 8;
    if constexpr (OMODE == 0) {
        float* C = (float*)Cout;
        #pragma unroll
        for (int j = 0; j < NTILES; j++) {
            int n = j * 8 + t * 2;
            if (n < Ntrue) {
                float2 bb = *(const float2*)(bias + n);
                float v0 = acc[j][0] + bb.x, v1 = acc[j][1] + bb.y;
                float v2 = acc[j][2] + bb.x, v3 = acc[j][3] + bb.y;
                if (RELU) {
                    v0 = fmaxf(v0, 0.f); v1 = fmaxf(v1, 0.f);
                    v2 = fmaxf(v2, 0.f); v3 = fmaxf(v3, 0.f);
                }
                *(float2*)(C + r0 * Ntrue + n) = make_float2(v0, v1);
                *(float2*)(C + r1 * Ntrue + n) = make_float2(v2, v3);
            }
        }
    } else {
        unsigned char* Cf = (unsigned char*)Cout;
        #pragma unroll
        for (int j = 0; j < NTILES; j++) {
            int n = j * 8 + t * 2;
            if (n < Ntrue) {
                float2 bb = *(const float2*)(bias + n);
                float v0 = acc[j][0] + bb.x, v1 = acc[j][1] + bb.y;
                float v2 = acc[j][2] + bb.x, v3 = acc[j][3] + bb.y;
                if (RELU) {
                    v0 = fmaxf(v0, 0.f); v1 = fmaxf(v1, 0.f);
                    v2 = fmaxf(v2, 0.f); v3 = fmaxf(v3, 0.f);
                }
                uint32_t hi, lo;
                uint32_t off = frag_off(n);
                split2(v0, v1, hi, lo);
                *(uint2*)(Cf + r0 * (size_t)o_rowstride + off) = make_uint2(hi, lo);
                split2(v2, v3, hi, lo);
                *(uint2*)(Cf + r1 * (size_t)o_rowstride + off) = make_uint2(hi, lo);
            }
        }
        // zero-fill padded k-range [padlo, padhi) for the consumer
        const int npad2 = (o_padhi - o_padlo) >> 1;
        for (int f = tid; f < 128 * npad2; f += 256) {
            int row = f / npad2;
            int idx = f - row * npad2;
            int n = o_padlo + 2 * idx;
            *(uint2*)(Cf + (m0 + row) * (size_t)o_rowstride + frag_off(n)) =
                make_uint2(0u, 0u);
        }
    }
}

// ---------------------------------------------------------------------------
// Quantum epilogue math (verified rounds 1-4), fast sincos.
// ---------------------------------------------------------------------------
__device__ __forceinline__ float2 cadd(float2 a, float2 b) {
    return make_float2(a.x + b.x, a.y + b.y);
}
__device__ __forceinline__ float2 csc(float s, float2 a) {
    return make_float2(s * a.x, s * a.y);
}
__device__ __forceinline__ float2 cni(float s, float2 a) {
    return make_float2(s * a.y, -s * a.x);
}

__device__ void applyU(const float* __restrict__ p, float2 x[4]) {
    float c4, s4;
    __sincosf(0.5f * p[4], &s4, &c4);
    float2 y1 = make_float2(c4 * x[1].x + s4 * x[3].y,
                            c4 * x[1].y - s4 * x[3].x);
    float2 y3 = make_float2(s4 * x[1].y + c4 * x[3].x,
                           -s4 * x[1].x + c4 * x[3].y);
    x[1] = y1; x[3] = y3;

    float c2, s2, c3, s3;
    __sincosf(0.5f * p[2], &s2, &c2);
    __sincosf(0.5f * p[3], &s3, &c3);
    float2 t00 = cadd(csc(c3, x[0]), csc(-s3, x[1]));
    float2 t01 = cadd(csc(s3, x[0]), csc( c3, x[1]));
    float2 t10 = cadd(csc(c3, x[2]), csc(-s3, x[3]));
    float2 t11 = cadd(csc(s3, x[2]), csc( c3, x[3]));
    x[0] = cadd(csc(c2, t00), csc(-s2, t10));
    x[1] = cadd(csc(c2, t01), csc(-s2, t11));
    x[2] = cadd(csc(s2, t00), csc( c2, t10));
    x[3] = cadd(csc(s2, t01), csc( c2, t11));

    float c1, s1;
    __sincosf(0.5f * p[1], &s1, &c1);
    float2 u00 = cadd(csc(c1, x[0]), cni(s1, x[1]));
    float2 u01 = cadd(cni(s1, x[0]), csc(c1, x[1]));
    float2 u10 = cadd(csc(c1, x[2]), cni(s1, x[3]));
    float2 u11 = cadd(cni(s1, x[2]), csc(c1, x[3]));
    x[0] = cadd(csc(c1, u00), cni(s1, u10));
    x[1] = cadd(csc(c1, u01), cni(s1, u11));
    x[2] = cadd(cni(s1, u00), csc(c1, u10));
    x[3] = cadd(cni(s1, u01), csc(c1, u11));
}

__device__ __forceinline__ float fidelity_from(const float* l1, const float* l2) {
    float2 s1[4] = {make_float2(1.f, 0.f), make_float2(0.f, 0.f),
                    make_float2(0.f, 0.f), make_float2(0.f, 0.f)};
    applyU(l1, s1);
    applyU(l1 + 5, s1);
    float2 s2[4] = {make_float2(1.f, 0.f), make_float2(0.f, 0.f),
                    make_float2(0.f, 0.f), make_float2(0.f, 0.f)};
    applyU(l2, s2);
    applyU(l2 + 5, s2);
    float re = 0.f, im = 0.f;
    #pragma unroll
    for (int i = 0; i < 4; i++) {
        re += s2[i].x * s1[i].x + s2[i].y * s1[i].y;
        im += s2[i].x * s1[i].y - s2[i].y * s1[i].x;
    }
    return re * re + im * im;
}

__global__ __launch_bounds__(128)
void l4_quantum(const float* __restrict__ H3, const float* __restrict__ W4,
                const float* __restrict__ b4, float* __restrict__ out) {
    __shared__ float hs[128][51];
    __shared__ float w4s[10][50];
    __shared__ float b4s[10];
    __shared__ float Ls[128][11];

    const int tid = threadIdx.x;
    const size_t base = (size_t)blockIdx.x * 128 * 50;

    for (int i = tid; i < 3200; i += 128) {
        float2 v = *(const float2*)&H3[base + 2 * (size_t)i];
        int row = (2 * i) / 50, col = (2 * i) % 50;
        hs[row][col] = v.x;
        hs[row][col + 1] = v.y;
    }
    for (int i = tid; i < 500; i += 128) w4s[i / 50][i % 50] = W4[i];
    if (tid < 10) b4s[tid] = b4[tid];
    __syncthreads();

    float l[10];
    #pragma unroll
    for (int j = 0; j < 10; j++) l[j] = b4s[j];
    #pragma unroll 5
    for (int k = 0; k < 50; k++) {
        float hv = hs[tid][k];
        #pragma unroll
        for (int j = 0; j < 10; j++) l[j] = fmaf(w4s[j][k], hv, l[j]);
    }
    #pragma unroll
    for (int j = 0; j < 10; j++) Ls[tid][j] = l[j];
    __syncthreads();

    if (tid < 64) {
        out[(size_t)blockIdx.x * 64 + tid] =
            fidelity_from(&Ls[2 * tid][0], &Ls[2 * tid + 1][0]);
    }
}

// ---------------------------------------------------------------------------
extern "C" void kernel_launch(void* const* d_in, const int* in_sizes, int n_in,
                              void* d_out, int out_size) {
    const float* x  = (const float*)d_in[0];
    const float* W1 = (const float*)d_in[1];
    const float* b1 = (const float*)d_in[2];
    const float* W2 = (const float*)d_in[3];
    const float* b2 = (const float*)d_in[4];
    const float* W3 = (const float*)d_in[5];
    const float* b3 = (const float*)d_in[6];
    const float* W4 = (const float*)d_in[7];
    const float* b4 = (const float*)d_in[8];
    float* out = (float*)d_out;

    unsigned char *h1f, *h2f, *w1f, *w2f, *w3f;
    float *h3;
    cudaGetSymbolAddress((void**)&h1f, g_h1f);
    cudaGetSymbolAddress((void**)&h2f, g_h2f);
    cudaGetSymbolAddress((void**)&h3,  g_h3);
    cudaGetSymbolAddress((void**)&w1f, g_w1f);
    cudaGetSymbolAddress((void**)&w2f, g_w2f);
    cudaGetSymbolAddress((void**)&w3f, g_w3f);

    // Pre-split weights into fragment images
    prep_w_frag<<<(200 * 10 * 8 + 255) / 256, 256>>>(W1, w1f, 200, 300, 10, 200 * 10 * 8);
    prep_w_frag<<<(104 * 7  * 8 + 255) / 256, 256>>>(W2, w2f, 100, 200, 7,  104 * 7  * 8);
    prep_w_frag<<<(56  * 4  * 8 + 255) / 256, 256>>>(W3, w3f, 50,  100, 4,  56  * 4  * 8);

    const int SM1 = 2 * (128 + 200) * ROWB;  // 125952
    const int SM2 = 2 * (128 + 104) * ROWB;  //  89088
    const int SM3 = 2 * (128 +  56) * ROWB;  //  70656
    cudaFuncSetAttribute(gemm_mma<25, 0, 1, true>,
                         cudaFuncAttributeMaxDynamicSharedMemorySize, SM1);
    cudaFuncSetAttribute(gemm_mma<13, 1, 1, true>,
                         cudaFuncAttributeMaxDynamicSharedMemorySize, SM2);
    cudaFuncSetAttribute(gemm_mma<7, 1, 0, true>,
                         cudaFuncAttributeMaxDynamicSharedMemorySize, SM3);

    const int MT = MROWS / 128;  // 1024
    // L1: A = x fp32 [2B,300], out -> h1 frag (stride 896), pad n [200,224)
    gemm_mma<25, 0, 1, true><<<MT, 256, SM1>>>(x, w1f, b1, h1f,
                                               200, 300, 10, 0, 896, 200, 224);
    // L2: A = h1 frag (stride 896), out -> h2 frag (stride 512), pad [104,128)
    gemm_mma<13, 1, 1, true><<<MT, 256, SM2>>>(h1f, w2f, b2, h2f,
                                               100, 200, 7, 896, 512, 104, 128);
    // L3: A = h2 frag (stride 512), out -> h3 fp32 [M,50]
    gemm_mma<7, 1, 0, true><<<MT, 256, SM3>>>(h2f, w3f, b3, h3,
                                              50, 100, 4, 512, 0, 0, 0);
    l4_quantum<<<MROWS / 128, 128>>>(h3, W4, b4, out);
}

// round 6
// speedup vs baseline: 5.9646x; 1.1988x over previous
#include <cuda_runtime.h>
#include <cuda_bf16.h>
#include <math.h>
#include <cstdint>

// ---------------------------------------------------------------------------
// PreQ via mma.sync m16n8k8 tf32 (single MMA, RN-rounded operands):
//  - x pre-rounded+permuted once into a fragment image (streaming prep)
//  - W pre-rounded+permuted once (tiny preps)
//  - intermediates written pre-permuted by the GEMM epilogue
//  - GEMM staging = pure cp.async; layer4+quantum fused into layer3
// Fragment 64B entry per row per k16: [t']*16B = {k=t', t'+4, t'+8, t'+12}
// ---------------------------------------------------------------------------

#define MROWS 131072   // 2 * 65536
#define ROWB  192      // smem row stride per 32-k chunk (128B data + 64B pad)

__device__ __align__(16) unsigned char g_xf [(size_t)MROWS * 1280]; // 10 chunks
__device__ __align__(16) unsigned char g_h1f[(size_t)MROWS * 896];  // 7 chunks
__device__ __align__(16) unsigned char g_h2f[(size_t)MROWS * 512];  // 4 chunks
__device__ __align__(16) unsigned char g_w1f[224 * 1280];
__device__ __align__(16) unsigned char g_w2f[112 * 896];
__device__ __align__(16) unsigned char g_w3f[64 * 512];

// ---------------------------------------------------------------------------
__device__ __forceinline__ uint32_t smem_u32(const void* p) {
    uint32_t a;
    asm("{ .reg .u64 t; cvta.to.shared.u64 t, %1; cvt.u32.u64 %0, t; }"
        : "=r"(a) : "l"(p));
    return a;
}
__device__ __forceinline__ void cpa16(uint32_t dst, const void* src) {
    asm volatile("cp.async.cg.shared.global [%0], [%1], 16;"
                 :: "r"(dst), "l"(src) : "memory");
}
#define CP_COMMIT() asm volatile("cp.async.commit_group;" ::: "memory")
#define CP_WAIT0()  asm volatile("cp.async.wait_group 0;" ::: "memory")

__device__ __forceinline__ uint32_t to_tf32(float f) {
    uint32_t r;
    asm("cvt.rna.tf32.f32 %0, %1;" : "=r"(r) : "f"(f));
    return r;
}

__device__ __forceinline__ void mma_tf32(float c[4],
                                         uint32_t a0, uint32_t a1,
                                         uint32_t a2, uint32_t a3,
                                         uint32_t b0, uint32_t b1) {
    asm volatile(
        "mma.sync.aligned.m16n8k8.row.col.f32.tf32.tf32.f32 "
        "{%0,%1,%2,%3}, {%4,%5,%6,%7}, {%8,%9}, {%0,%1,%2,%3};"
        : "+f"(c[0]), "+f"(c[1]), "+f"(c[2]), "+f"(c[3])
        : "r"(a0), "r"(a1), "r"(a2), "r"(a3), "r"(b0), "r"(b1));
}

// ---------------------------------------------------------------------------
// prep: S[src_rows, K] fp32 -> frag image [nrows_pad][nblk * 64B], RN tf32.
// One thread per 64B entry (row, k16-block): 4x LDG.128 -> cvt -> 4x STG.128.
// ---------------------------------------------------------------------------
__global__ void prep_frag(const float* __restrict__ S,
                          unsigned char* __restrict__ D,
                          int nrows_pad, int src_rows, int K, int nblk) {
    int f = blockIdx.x * blockDim.x + threadIdx.x;
    int total = nrows_pad * nblk;
    if (f >= total) return;
    int row = f / nblk, eb = f - row * nblk;
    int k0 = eb * 16;
    float v[16];
    #pragma unroll
    for (int i = 0; i < 16; i++) v[i] = 0.f;
    if (row < src_rows) {
        #pragma unroll
        for (int i = 0; i < 4; i++) {
            int k = k0 + i * 4;
            if (k < K) {
                float4 q = *(const float4*)(S + (size_t)row * K + k);
                v[i * 4 + 0] = q.x; v[i * 4 + 1] = q.y;
                v[i * 4 + 2] = q.z; v[i * 4 + 3] = q.w;
            }
        }
    }
    uint32_t u[16];
    #pragma unroll
    for (int i = 0; i < 16; i++) u[i] = to_tf32(v[i]);
    unsigned char* dst = D + (size_t)row * (nblk * 64) + (size_t)eb * 64;
    #pragma unroll
    for (int tp = 0; tp < 4; tp++)
        *(uint4*)(dst + tp * 16) =
            make_uint4(u[tp], u[tp + 4], u[tp + 8], u[tp + 12]);
}

// ---------------------------------------------------------------------------
// Quantum epilogue math (verified rounds 1-5).
// ---------------------------------------------------------------------------
__device__ __forceinline__ float2 cadd(float2 a, float2 b) {
    return make_float2(a.x + b.x, a.y + b.y);
}
__device__ __forceinline__ float2 csc(float s, float2 a) {
    return make_float2(s * a.x, s * a.y);
}
__device__ __forceinline__ float2 cni(float s, float2 a) {
    return make_float2(s * a.y, -s * a.x);
}

__device__ void applyU(const float* __restrict__ p, float2 x[4]) {
    float c4, s4;
    __sincosf(0.5f * p[4], &s4, &c4);
    float2 y1 = make_float2(c4 * x[1].x + s4 * x[3].y,
                            c4 * x[1].y - s4 * x[3].x);
    float2 y3 = make_float2(s4 * x[1].y + c4 * x[3].x,
                           -s4 * x[1].x + c4 * x[3].y);
    x[1] = y1; x[3] = y3;

    float c2, s2, c3, s3;
    __sincosf(0.5f * p[2], &s2, &c2);
    __sincosf(0.5f * p[3], &s3, &c3);
    float2 t00 = cadd(csc(c3, x[0]), csc(-s3, x[1]));
    float2 t01 = cadd(csc(s3, x[0]), csc( c3, x[1]));
    float2 t10 = cadd(csc(c3, x[2]), csc(-s3, x[3]));
    float2 t11 = cadd(csc(s3, x[2]), csc( c3, x[3]));
    x[0] = cadd(csc(c2, t00), csc(-s2, t10));
    x[1] = cadd(csc(c2, t01), csc(-s2, t11));
    x[2] = cadd(csc(s2, t00), csc( c2, t10));
    x[3] = cadd(csc(s2, t01), csc( c2, t11));

    float c1, s1;
    __sincosf(0.5f * p[1], &s1, &c1);
    float2 u00 = cadd(csc(c1, x[0]), cni(s1, x[1]));
    float2 u01 = cadd(cni(s1, x[0]), csc(c1, x[1]));
    float2 u10 = cadd(csc(c1, x[2]), cni(s1, x[3]));
    float2 u11 = cadd(cni(s1, x[2]), csc(c1, x[3]));
    x[0] = cadd(csc(c1, u00), cni(s1, u10));
    x[1] = cadd(csc(c1, u01), cni(s1, u11));
    x[2] = cadd(cni(s1, u00), csc(c1, u10));
    x[3] = cadd(cni(s1, u01), csc(c1, u11));
}

__device__ __forceinline__ float fidelity_from(const float* l1, const float* l2) {
    float2 s1[4] = {make_float2(1.f, 0.f), make_float2(0.f, 0.f),
                    make_float2(0.f, 0.f), make_float2(0.f, 0.f)};
    applyU(l1, s1);
    applyU(l1 + 5, s1);
    float2 s2[4] = {make_float2(1.f, 0.f), make_float2(0.f, 0.f),
                    make_float2(0.f, 0.f), make_float2(0.f, 0.f)};
    applyU(l2, s2);
    applyU(l2 + 5, s2);
    float re = 0.f, im = 0.f;
    #pragma unroll
    for (int i = 0; i < 4; i++) {
        re += s2[i].x * s1[i].x + s2[i].y * s1[i].y;
        im += s2[i].x * s1[i].y - s2[i].y * s1[i].x;
    }
    return re * re + im * im;
}

// ---------------------------------------------------------------------------
// tf32 GEMM: 128 rows/CTA, 8 warps = 4 m-warps (m32 each) x 2 n-warps
// (NWT n8-tiles each). K in 32-k chunks, double-buffered cp.async staging.
// OMODE 1: frag-image output (+ optional zero block). OMODE 2: fused
// layer4 (50->10) + quantum fidelity output.
// ---------------------------------------------------------------------------
template<int NWT, int OMODE>
__global__ __launch_bounds__(256, 2)
void gemm_tf32(const unsigned char* __restrict__ Af,
               const unsigned char* __restrict__ Wf,
               const float* __restrict__ bias, void* __restrict__ Out,
               int Ntrue, int nch, int a_rowb, int w_rowb, int o_rowb,
               int zeroblk,
               const float* __restrict__ W4, const float* __restrict__ b4) {
    extern __shared__ __align__(16) char sm[];
    constexpr int NTC   = NWT * 16;          // CTA n-columns
    constexpr int ABY   = 128 * ROWB;        // 24576
    constexpr int STAGE = ABY + NTC * ROWB;
    constexpr int CSS   = (OMODE == 1) ? 116 : 68;   // Cs row stride (floats)

    const uint32_t sb = smem_u32(sm);
    const int tid  = threadIdx.x;
    const int wid  = tid >> 5;
    const int lane = tid & 31;
    const int g    = lane >> 2;
    const int t    = lane & 3;
    const int mw   = wid & 3;                // m-warp: rows [mw*32, mw*32+32)
    const int nw   = wid >> 2;               // n-warp: tiles [nw*NWT, ...)
    const size_t m0 = (size_t)blockIdx.x * 128;
    const int n0  = blockIdx.y * NTC;
    const int blk0 = blockIdx.y * NWT;

    float acc[2][NWT][4];
    #pragma unroll
    for (int mt = 0; mt < 2; mt++)
        #pragma unroll
        for (int j = 0; j < NWT; j++)
            #pragma unroll
            for (int p = 0; p < 4; p++) acc[mt][j][p] = 0.f;

    auto stage = [&](int c, int slot) {
        const uint32_t bufb = sb + slot * STAGE;
        // A: 128 rows x 8 x 16B
        #pragma unroll
        for (int i = 0; i < 4; i++) {
            int f = tid + i * 256;
            int row = f >> 3, e = f & 7;
            cpa16(bufb + row * ROWB + e * 16,
                  Af + (m0 + row) * (size_t)a_rowb + c * 128 + e * 16);
        }
        // W: NTC rows x 8 x 16B
        constexpr int WF = NTC * 8;
        #pragma unroll
        for (int i = 0; i < (WF + 255) / 256; i++) {
            int f = tid + i * 256;
            if (f < WF) {
                int row = f >> 3, e = f & 7;
                cpa16(bufb + ABY + row * ROWB + e * 16,
                      Wf + (size_t)(n0 + row) * w_rowb + c * 128 + e * 16);
            }
        }
    };

    auto compute = [&](int slot) {
        char* As = sm + slot * STAGE;
        char* Ws = As + ABY;
        #pragma unroll
        for (int s = 0; s < 2; s++) {
            // A fragments: rows (g, g+8) of both m16 tiles; 16B = k {t,t+4,t+8,t+12}
            uint4 a0g  = *(const uint4*)(As + (mw * 32 +      g) * ROWB + s * 64 + t * 16);
            uint4 a0g8 = *(const uint4*)(As + (mw * 32 +  8 + g) * ROWB + s * 64 + t * 16);
            uint4 a1g  = *(const uint4*)(As + (mw * 32 + 16 + g) * ROWB + s * 64 + t * 16);
            uint4 a1g8 = *(const uint4*)(As + (mw * 32 + 24 + g) * ROWB + s * 64 + t * 16);
            #pragma unroll
            for (int j = 0; j < NWT; j++) {
                uint4 bb = *(const uint4*)(Ws + ((nw * NWT + j) * 8 + g) * ROWB + s * 64 + t * 16);
                // k8 step u=0: a = (.x row g / g+8, .y = k+4), b = (.x, .y)
                mma_tf32(acc[0][j], a0g.x, a0g8.x, a0g.y, a0g8.y, bb.x, bb.y);
                mma_tf32(acc[1][j], a1g.x, a1g8.x, a1g.y, a1g8.y, bb.x, bb.y);
                // k8 step u=1
                mma_tf32(acc[0][j], a0g.z, a0g8.z, a0g.w, a0g8.w, bb.z, bb.w);
                mma_tf32(acc[1][j], a1g.z, a1g8.z, a1g.w, a1g8.w, bb.z, bb.w);
            }
        }
    };

    stage(0, 0);
    CP_COMMIT();
    CP_WAIT0();
    __syncthreads();
    for (int c = 0; c < nch; ++c) {
        if (c + 1 < nch) { stage(c + 1, (c + 1) & 1); CP_COMMIT(); }
        compute(c & 1);
        CP_WAIT0();
        __syncthreads();
    }

    // ---- write accumulators (bias + ReLU) to Cs fp32 in smem ----
    float* Cs = (float*)sm;
    #pragma unroll
    for (int mt = 0; mt < 2; mt++) {
        int r = mw * 32 + mt * 16 + g;
        #pragma unroll
        for (int j = 0; j < NWT; j++) {
            int nl = (nw * NWT + j) * 8 + 2 * t;
            int n = n0 + nl;
            float bx = (n     < Ntrue) ? bias[n]     : 0.f;
            float by = (n + 1 < Ntrue) ? bias[n + 1] : 0.f;
            float v0 = fmaxf(acc[mt][j][0] + bx, 0.f);
            float v1 = fmaxf(acc[mt][j][1] + by, 0.f);
            float v2 = fmaxf(acc[mt][j][2] + bx, 0.f);
            float v3 = fmaxf(acc[mt][j][3] + by, 0.f);
            *(float2*)(Cs + r * CSS + nl)       = make_float2(v0, v1);
            *(float2*)(Cs + (r + 8) * CSS + nl) = make_float2(v2, v3);
        }
    }
    __syncthreads();

    if constexpr (OMODE == 1) {
        // repack Cs -> frag image (RN tf32 + perm), full 16B stores
        unsigned char* Cf = (unsigned char*)Out;
        constexpr int NBLK = NWT;   // per-CTA k16 blocks = NTC/16
        for (int f = tid; f < 128 * NBLK; f += 256) {
            int row = f / NBLK, eb = f - row * NBLK;
            const float* src = Cs + row * CSS + eb * 16;
            float4 q0 = *(const float4*)(src + 0);
            float4 q1 = *(const float4*)(src + 4);
            float4 q2 = *(const float4*)(src + 8);
            float4 q3 = *(const float4*)(src + 12);
            uint32_t u[16] = {
                to_tf32(q0.x), to_tf32(q0.y), to_tf32(q0.z), to_tf32(q0.w),
                to_tf32(q1.x), to_tf32(q1.y), to_tf32(q1.z), to_tf32(q1.w),
                to_tf32(q2.x), to_tf32(q2.y), to_tf32(q2.z), to_tf32(q2.w),
                to_tf32(q3.x), to_tf32(q3.y), to_tf32(q3.z), to_tf32(q3.w)};
            unsigned char* dst = Cf + (m0 + row) * (size_t)o_rowb + (blk0 + eb) * 64;
            #pragma unroll
            for (int tp = 0; tp < 4; tp++)
                *(uint4*)(dst + tp * 16) =
                    make_uint4(u[tp], u[tp + 4], u[tp + 8], u[tp + 12]);
        }
        if (zeroblk >= 0) {
            for (int f = tid; f < 128 * 4; f += 256) {
                int row = f >> 2, q = f & 3;
                *(uint4*)(Cf + (m0 + row) * (size_t)o_rowb + zeroblk * 64 + q * 16) =
                    make_uint4(0u, 0u, 0u, 0u);
            }
        }
    } else {
        // fused layer4 (50->10, no relu) + quantum fidelity
        float* w4s = (float*)(sm + 128 * CSS * 4);        // 500 floats
        float* b4s = w4s + 500;                           // 10
        float* Ls  = (float*)(sm + 128 * CSS * 4 + 2048); // [128][11]
        for (int i = tid; i < 500; i += 256) w4s[i] = W4[i];
        if (tid < 10) b4s[tid] = b4[tid];
        __syncthreads();

        if (tid < 128) {
            float l[10];
            #pragma unroll
            for (int j = 0; j < 10; j++) l[j] = b4s[j];
            #pragma unroll 5
            for (int k = 0; k < 50; k++) {
                float hv = Cs[tid * CSS + k];
                #pragma unroll
                for (int j = 0; j < 10; j++) l[j] = fmaf(w4s[j * 50 + k], hv, l[j]);
            }
            #pragma unroll
            for (int j = 0; j < 10; j++) Ls[tid * 11 + j] = l[j];
        }
        __syncthreads();
        if (tid < 64) {
            ((float*)Out)[(size_t)blockIdx.x * 64 + tid] =
                fidelity_from(Ls + 2 * tid * 11, Ls + (2 * tid + 1) * 11);
        }
    }
}

// ---------------------------------------------------------------------------
extern "C" void kernel_launch(void* const* d_in, const int* in_sizes, int n_in,
                              void* d_out, int out_size) {
    const float* x  = (const float*)d_in[0];
    const float* W1 = (const float*)d_in[1];
    const float* b1 = (const float*)d_in[2];
    const float* W2 = (const float*)d_in[3];
    const float* b2 = (const float*)d_in[4];
    const float* W3 = (const float*)d_in[5];
    const float* b3 = (const float*)d_in[6];
    const float* W4 = (const float*)d_in[7];
    const float* b4 = (const float*)d_in[8];

    unsigned char *xf, *h1f, *h2f, *w1f, *w2f, *w3f;
    cudaGetSymbolAddress((void**)&xf,  g_xf);
    cudaGetSymbolAddress((void**)&h1f, g_h1f);
    cudaGetSymbolAddress((void**)&h2f, g_h2f);
    cudaGetSymbolAddress((void**)&w1f, g_w1f);
    cudaGetSymbolAddress((void**)&w2f, g_w2f);
    cudaGetSymbolAddress((void**)&w3f, g_w3f);

    // Preps: RN tf32 + fragment permutation
    prep_frag<<<(MROWS * 20 + 255) / 256, 256>>>(x,  xf,  MROWS, MROWS, 300, 20);
    prep_frag<<<(224 * 20 + 255) / 256, 256>>>(W1, w1f, 224, 200, 300, 20);
    prep_frag<<<(112 * 14 + 255) / 256, 256>>>(W2, w2f, 112, 100, 200, 14);
    prep_frag<<<(64  *  8 + 255) / 256, 256>>>(W3, w3f, 64,  50,  100, 8);

    constexpr int SM12 = (128 + 112) * ROWB * 2;  // 92160
    constexpr int SM3  = (128 +  64) * ROWB * 2;  // 73728
    cudaFuncSetAttribute(gemm_tf32<7, 1>,
                         cudaFuncAttributeMaxDynamicSharedMemorySize, SM12);
    cudaFuncSetAttribute(gemm_tf32<4, 2>,
                         cudaFuncAttributeMaxDynamicSharedMemorySize, SM3);

    const int MT = MROWS / 128;   // 1024
    // L1: A = xf (1280B/row), W = w1f (1280B/row), out h1f (896B/row), N split 2
    gemm_tf32<7, 1><<<dim3(MT, 2), 256, SM12>>>(xf, w1f, b1, h1f,
                                                200, 10, 1280, 1280, 896, -1,
                                                nullptr, nullptr);
    // L2: A = h1f, W = w2f (896B/row), out h2f (512B/row), zero block 7
    gemm_tf32<7, 1><<<dim3(MT, 1), 256, SM12>>>(h1f, w2f, b2, h2f,
                                                100, 7, 896, 896, 512, 7,
                                                nullptr, nullptr);
    // L3: A = h2f, W = w3f (512B/row), fused layer4 + fidelity -> d_out
    gemm_tf32<4, 2><<<dim3(MT, 1), 256, SM3>>>(h2f, w3f, b3, d_out,
                                               50, 4, 512, 512, 0, -1,
                                               W4, b4);
}